// round 6
// baseline (speedup 1.0000x reference)
#include <cuda_runtime.h>
#include <cuda_bf16.h>

// Sorted segment-sum: feat [N,128] f32, segment_ids [N] i32 (non-decreasing),
// out [4096,128] f32.
//
// R5 changes vs R4 (94.3us, DRAM 73%):
//  - uniform-chunk fast path: if seg[row0]==seg[row_end-1], stream 128 rows
//    with zero id loads and no branches (hits ~52% of chunks).
//  - mixed path preloads all 16 group-last ids in ONE coalesced load and
//    distributes via shfl -> no dependent id load per iteration.
//  - flush uses red.global.add.v4.f32 (1 instr instead of 4 atomicAdds).
//  - #pragma unroll 2 on streaming loops for cross-iteration load overlap.

#define D_FEAT 128
#define LANES_F4 (D_FEAT / 4)      // 32 float4 per row == 32 lanes
#define ROWS_PER_WARP 128
#define GROUPS (ROWS_PER_WARP / 8) // 16
#define THREADS_PER_BLOCK 256
#define WARPS_PER_BLOCK (THREADS_PER_BLOCK / 32)

__global__ void zero_out_kernel(float4* __restrict__ out, int n4) {
    int i = blockIdx.x * blockDim.x + threadIdx.x;
    if (i < n4) out[i] = make_float4(0.f, 0.f, 0.f, 0.f);
}

__device__ __forceinline__ void red_flush(float* __restrict__ out, int segid,
                                          int lane, float4& acc) {
    float* dst = out + (size_t)segid * D_FEAT + lane * 4;   // 16B aligned
    asm volatile("red.global.add.v4.f32 [%0], {%1, %2, %3, %4};"
                 :: "l"(dst), "f"(acc.x), "f"(acc.y), "f"(acc.z), "f"(acc.w)
                 : "memory");
    acc = make_float4(0.f, 0.f, 0.f, 0.f);
}

// Sum 8 consecutive rows (pairwise tree) into acc. p points at row r, lane's f4.
__device__ __forceinline__ void sum8(const float4* __restrict__ p, float4& acc) {
    float4 v0 = __ldg(p + 0 * LANES_F4);
    float4 v1 = __ldg(p + 1 * LANES_F4);
    float4 v2 = __ldg(p + 2 * LANES_F4);
    float4 v3 = __ldg(p + 3 * LANES_F4);
    float4 v4 = __ldg(p + 4 * LANES_F4);
    float4 v5 = __ldg(p + 5 * LANES_F4);
    float4 v6 = __ldg(p + 6 * LANES_F4);
    float4 v7 = __ldg(p + 7 * LANES_F4);
    float4 s01, s23, s45, s67, s03, s47;
    s01.x = v0.x + v1.x; s01.y = v0.y + v1.y; s01.z = v0.z + v1.z; s01.w = v0.w + v1.w;
    s23.x = v2.x + v3.x; s23.y = v2.y + v3.y; s23.z = v2.z + v3.z; s23.w = v2.w + v3.w;
    s45.x = v4.x + v5.x; s45.y = v4.y + v5.y; s45.z = v4.z + v5.z; s45.w = v4.w + v5.w;
    s67.x = v6.x + v7.x; s67.y = v6.y + v7.y; s67.z = v6.z + v7.z; s67.w = v6.w + v7.w;
    s03.x = s01.x + s23.x; s03.y = s01.y + s23.y; s03.z = s01.z + s23.z; s03.w = s01.w + s23.w;
    s47.x = s45.x + s67.x; s47.y = s45.y + s67.y; s47.z = s45.z + s67.z; s47.w = s45.w + s67.w;
    acc.x += s03.x + s47.x;
    acc.y += s03.y + s47.y;
    acc.z += s03.z + s47.z;
    acc.w += s03.w + s47.w;
}

__global__ __launch_bounds__(THREADS_PER_BLOCK)
void segment_sum_kernel(const float4* __restrict__ feat4,
                        const int* __restrict__ seg,
                        float* __restrict__ out,
                        int n_rows) {
    const int warp_global = (blockIdx.x * WARPS_PER_BLOCK) + (threadIdx.x >> 5);
    const int lane = threadIdx.x & 31;

    const int row0 = warp_global * ROWS_PER_WARP;
    if (row0 >= n_rows) return;
    int row_end = row0 + ROWS_PER_WARP;
    if (row_end > n_rows) row_end = n_rows;

    float4 acc = make_float4(0.f, 0.f, 0.f, 0.f);
    const int first = __ldg(seg + row0);
    const int last  = __ldg(seg + row_end - 1);

    if (first == last && row_end == row0 + ROWS_PER_WARP) {
        // ---- uniform full chunk: branch-free stream, no id loads ----
        const float4* p = feat4 + (size_t)row0 * LANES_F4 + lane;
        #pragma unroll 2
        for (int it = 0; it < GROUPS; ++it) {
            sum8(p, acc);
            p += 8 * LANES_F4;
        }
        red_flush(out, first, lane, acc);
        return;
    }

    // ---- mixed chunk: preload all 16 group-last ids in one coalesced load ----
    int gid = -1;
    {
        int gr = row0 + 8 * lane + 7;            // lane j -> last row of group j
        if (lane < GROUPS && gr < n_rows) gid = __ldg(seg + gr);
    }

    int cur = first;
    int r = row0;
    #pragma unroll 2
    for (int j = 0; j < GROUPS; ++j) {
        if (r >= row_end) break;
        int g = __shfl_sync(0xffffffffu, gid, j);
        if (r + 8 <= row_end && g == cur) {
            sum8(feat4 + (size_t)r * LANES_F4 + lane, acc);
            r += 8;
        } else {
            int stop = r + 8;
            if (stop > row_end) stop = row_end;
            for (; r < stop; ++r) {
                int sid = __ldg(seg + r);
                if (sid != cur) {
                    red_flush(out, cur, lane, acc);
                    cur = sid;
                }
                float4 v = __ldg(feat4 + (size_t)r * LANES_F4 + lane);
                acc.x += v.x; acc.y += v.y; acc.z += v.z; acc.w += v.w;
            }
        }
    }
    red_flush(out, cur, lane, acc);
}

extern "C" void kernel_launch(void* const* d_in, const int* in_sizes, int n_in,
                              void* d_out, int out_size) {
    const float* feat = (const float*)d_in[0];
    const int* seg = (const int*)d_in[1];
    float* out = (float*)d_out;

    const int n_rows = in_sizes[1];            // segment_ids element count

    // 1) zero the (poisoned) output
    int n4 = out_size / 4;
    zero_out_kernel<<<(n4 + THREADS_PER_BLOCK - 1) / THREADS_PER_BLOCK,
                      THREADS_PER_BLOCK>>>((float4*)out, n4);

    // 2) segment sum
    int total_warps = (n_rows + ROWS_PER_WARP - 1) / ROWS_PER_WARP;
    int blocks = (total_warps + WARPS_PER_BLOCK - 1) / WARPS_PER_BLOCK;
    segment_sum_kernel<<<blocks, THREADS_PER_BLOCK>>>(
        (const float4*)feat, seg, out, n_rows);
}

// round 7
// speedup vs baseline: 1.1626x; 1.1626x over previous
#include <cuda_runtime.h>
#include <cuda_bf16.h>

// Sorted segment-sum: feat [N,128] f32, segment_ids [N] i32 (non-decreasing),
// out [4096,128] f32.
//
// R6: revert to R4's proven control flow (R5's restructure regressed).
// Changes vs R4 (94.3us total, DRAM 73%, occ 72% grid-limited at 977 blocks):
//  - ROWS_PER_WARP 128 -> 112: grid 977 -> 1117 blocks, fills the single
//    wave (148 SMs x 8 blocks/SM = 1184 capacity) -> occ ~92%, more
//    outstanding loads per SM for the latency-bound stream.
//  - flush via one red.global.add.v4.f32 instead of 4 atomicAdds.

#define D_FEAT 128
#define LANES_F4 (D_FEAT / 4)      // 32 float4 per row == 32 lanes
#define ROWS_PER_WARP 112
#define THREADS_PER_BLOCK 256
#define WARPS_PER_BLOCK (THREADS_PER_BLOCK / 32)

__global__ void zero_out_kernel(float4* __restrict__ out, int n4) {
    int i = blockIdx.x * blockDim.x + threadIdx.x;
    if (i < n4) out[i] = make_float4(0.f, 0.f, 0.f, 0.f);
}

__device__ __forceinline__ void red_flush(float* __restrict__ out, int segid,
                                          int lane, float4& acc) {
    float* dst = out + (size_t)segid * D_FEAT + lane * 4;   // 16B aligned
    asm volatile("red.global.add.v4.f32 [%0], {%1, %2, %3, %4};"
                 :: "l"(dst), "f"(acc.x), "f"(acc.y), "f"(acc.z), "f"(acc.w)
                 : "memory");
    acc = make_float4(0.f, 0.f, 0.f, 0.f);
}

__global__ __launch_bounds__(THREADS_PER_BLOCK)
void segment_sum_kernel(const float4* __restrict__ feat4,
                        const int* __restrict__ seg,
                        float* __restrict__ out,
                        int n_rows) {
    const int warp_global = (blockIdx.x * WARPS_PER_BLOCK) + (threadIdx.x >> 5);
    const int lane = threadIdx.x & 31;

    int row0 = warp_global * ROWS_PER_WARP;
    if (row0 >= n_rows) return;
    int row_end = row0 + ROWS_PER_WARP;
    if (row_end > n_rows) row_end = n_rows;

    float4 acc = make_float4(0.f, 0.f, 0.f, 0.f);
    int cur = __ldg(seg + row0);

    int r = row0;
    while (r < row_end) {
        if (r + 8 <= row_end && __ldg(seg + r + 7) == cur) {
            // Fast path: all 8 rows in segment `cur`. 8 independent loads.
            const float4* p = feat4 + (size_t)r * LANES_F4 + lane;
            float4 v0 = __ldg(p + 0 * LANES_F4);
            float4 v1 = __ldg(p + 1 * LANES_F4);
            float4 v2 = __ldg(p + 2 * LANES_F4);
            float4 v3 = __ldg(p + 3 * LANES_F4);
            float4 v4 = __ldg(p + 4 * LANES_F4);
            float4 v5 = __ldg(p + 5 * LANES_F4);
            float4 v6 = __ldg(p + 6 * LANES_F4);
            float4 v7 = __ldg(p + 7 * LANES_F4);
            // pairwise tree to shorten the dependent-add chain
            float4 s01, s23, s45, s67, s03, s47;
            s01.x = v0.x + v1.x; s01.y = v0.y + v1.y; s01.z = v0.z + v1.z; s01.w = v0.w + v1.w;
            s23.x = v2.x + v3.x; s23.y = v2.y + v3.y; s23.z = v2.z + v3.z; s23.w = v2.w + v3.w;
            s45.x = v4.x + v5.x; s45.y = v4.y + v5.y; s45.z = v4.z + v5.z; s45.w = v4.w + v5.w;
            s67.x = v6.x + v7.x; s67.y = v6.y + v7.y; s67.z = v6.z + v7.z; s67.w = v6.w + v7.w;
            s03.x = s01.x + s23.x; s03.y = s01.y + s23.y; s03.z = s01.z + s23.z; s03.w = s01.w + s23.w;
            s47.x = s45.x + s67.x; s47.y = s45.y + s67.y; s47.z = s45.z + s67.z; s47.w = s45.w + s67.w;
            acc.x += s03.x + s47.x;
            acc.y += s03.y + s47.y;
            acc.z += s03.z + s47.z;
            acc.w += s03.w + s47.w;
            r += 8;
        } else {
            // Slow path: segment boundary within the next 8 rows (or tail).
            int sid = __ldg(seg + r);
            if (sid != cur) {
                red_flush(out, cur, lane, acc);
                cur = sid;
            }
            float4 v = __ldg(feat4 + (size_t)r * LANES_F4 + lane);
            acc.x += v.x; acc.y += v.y; acc.z += v.z; acc.w += v.w;
            r += 1;
        }
    }
    red_flush(out, cur, lane, acc);
}

extern "C" void kernel_launch(void* const* d_in, const int* in_sizes, int n_in,
                              void* d_out, int out_size) {
    const float* feat = (const float*)d_in[0];
    const int* seg = (const int*)d_in[1];
    float* out = (float*)d_out;

    const int n_rows = in_sizes[1];            // segment_ids element count

    // 1) zero the (poisoned) output
    int n4 = out_size / 4;
    zero_out_kernel<<<(n4 + THREADS_PER_BLOCK - 1) / THREADS_PER_BLOCK,
                      THREADS_PER_BLOCK>>>((float4*)out, n4);

    // 2) segment sum
    int total_warps = (n_rows + ROWS_PER_WARP - 1) / ROWS_PER_WARP;
    int blocks = (total_warps + WARPS_PER_BLOCK - 1) / WARPS_PER_BLOCK;
    segment_sum_kernel<<<blocks, THREADS_PER_BLOCK>>>(
        (const float4*)feat, seg, out, n_rows);
}

// round 10
// speedup vs baseline: 1.1974x; 1.0299x over previous
#include <cuda_runtime.h>
#include <cuda_bf16.h>

// Sorted segment-sum: feat [N,128] f32, segment_ids [N] i32 (non-decreasing),
// out [4096,128] f32.
//
// R7 changes vs R6 (88.2us total / 85.9us kernel, DRAM 77.2%, occ 82.6%):
//  - ROWS_PER_WARP 112 -> 106: grid 1117 -> 1180 blocks, 99.7% of the
//    single-wave capacity (148 SMs x 8 blocks/SM = 1184 at regs=32).
//  - feat loads via __ldcs (evict-first): data is read-once; keep L2 for
//    segment-id lines and output atomics.
//  - zero-fill via cudaMemsetAsync instead of a kernel launch.
// Loop body unchanged from R4/R6 (regs must stay at 32: 8x256x32 = full RF).

#define D_FEAT 128
#define LANES_F4 (D_FEAT / 4)      // 32 float4 per row == 32 lanes
#define ROWS_PER_WARP 106
#define THREADS_PER_BLOCK 256
#define WARPS_PER_BLOCK (THREADS_PER_BLOCK / 32)

__device__ __forceinline__ void red_flush(float* __restrict__ out, int segid,
                                          int lane, float4& acc) {
    float* dst = out + (size_t)segid * D_FEAT + lane * 4;   // 16B aligned
    asm volatile("red.global.add.v4.f32 [%0], {%1, %2, %3, %4};"
                 :: "l"(dst), "f"(acc.x), "f"(acc.y), "f"(acc.z), "f"(acc.w)
                 : "memory");
    acc = make_float4(0.f, 0.f, 0.f, 0.f);
}

__global__ __launch_bounds__(THREADS_PER_BLOCK)
void segment_sum_kernel(const float4* __restrict__ feat4,
                        const int* __restrict__ seg,
                        float* __restrict__ out,
                        int n_rows) {
    const int warp_global = (blockIdx.x * WARPS_PER_BLOCK) + (threadIdx.x >> 5);
    const int lane = threadIdx.x & 31;

    int row0 = warp_global * ROWS_PER_WARP;
    if (row0 >= n_rows) return;
    int row_end = row0 + ROWS_PER_WARP;
    if (row_end > n_rows) row_end = n_rows;

    float4 acc = make_float4(0.f, 0.f, 0.f, 0.f);
    int cur = __ldg(seg + row0);

    int r = row0;
    while (r < row_end) {
        if (r + 8 <= row_end && __ldg(seg + r + 7) == cur) {
            // Fast path: all 8 rows in segment `cur`. 8 independent loads,
            // evict-first (read-once stream).
            const float4* p = feat4 + (size_t)r * LANES_F4 + lane;
            float4 v0 = __ldcs(p + 0 * LANES_F4);
            float4 v1 = __ldcs(p + 1 * LANES_F4);
            float4 v2 = __ldcs(p + 2 * LANES_F4);
            float4 v3 = __ldcs(p + 3 * LANES_F4);
            float4 v4 = __ldcs(p + 4 * LANES_F4);
            float4 v5 = __ldcs(p + 5 * LANES_F4);
            float4 v6 = __ldcs(p + 6 * LANES_F4);
            float4 v7 = __ldcs(p + 7 * LANES_F4);
            // pairwise tree to shorten the dependent-add chain
            float4 s01, s23, s45, s67, s03, s47;
            s01.x = v0.x + v1.x; s01.y = v0.y + v1.y; s01.z = v0.z + v1.z; s01.w = v0.w + v1.w;
            s23.x = v2.x + v3.x; s23.y = v2.y + v3.y; s23.z = v2.z + v3.z; s23.w = v2.w + v3.w;
            s45.x = v4.x + v5.x; s45.y = v4.y + v5.y; s45.z = v4.z + v5.z; s45.w = v4.w + v5.w;
            s67.x = v6.x + v7.x; s67.y = v6.y + v7.y; s67.z = v6.z + v7.z; s67.w = v6.w + v7.w;
            s03.x = s01.x + s23.x; s03.y = s01.y + s23.y; s03.z = s01.z + s23.z; s03.w = s01.w + s23.w;
            s47.x = s45.x + s67.x; s47.y = s45.y + s67.y; s47.z = s45.z + s67.z; s47.w = s45.w + s67.w;
            acc.x += s03.x + s47.x;
            acc.y += s03.y + s47.y;
            acc.z += s03.z + s47.z;
            acc.w += s03.w + s47.w;
            r += 8;
        } else {
            // Slow path: segment boundary within the next 8 rows (or tail).
            int sid = __ldg(seg + r);
            if (sid != cur) {
                red_flush(out, cur, lane, acc);
                cur = sid;
            }
            float4 v = __ldcs(feat4 + (size_t)r * LANES_F4 + lane);
            acc.x += v.x; acc.y += v.y; acc.z += v.z; acc.w += v.w;
            r += 1;
        }
    }
    red_flush(out, cur, lane, acc);
}

extern "C" void kernel_launch(void* const* d_in, const int* in_sizes, int n_in,
                              void* d_out, int out_size) {
    const float* feat = (const float*)d_in[0];
    const int* seg = (const int*)d_in[1];
    float* out = (float*)d_out;

    const int n_rows = in_sizes[1];            // segment_ids element count

    // 1) zero the (poisoned) output — memset node, graph-capturable
    cudaMemsetAsync(out, 0, (size_t)out_size * sizeof(float));

    // 2) segment sum
    int total_warps = (n_rows + ROWS_PER_WARP - 1) / ROWS_PER_WARP;
    int blocks = (total_warps + WARPS_PER_BLOCK - 1) / WARPS_PER_BLOCK;
    segment_sum_kernel<<<blocks, THREADS_PER_BLOCK>>>(
        (const float4*)feat, seg, out, n_rows);
}